// round 10
// baseline (speedup 1.0000x reference)
#include <cuda_runtime.h>

#define N_NODES 50000
#define N_EDGES 800000
#define D 64
#define GRID 592                         // 148 SMs x 4 blocks/SM
#define TPB 256
#define TILE 64
#define NT ((N_NODES + TILE - 1) / TILE) // 782 tiles of 64 rows
#define CH ((N_NODES + GRID - 1) / GRID) // 85 nodes per block chunk
#define AT_ST 68                         // smem tile stride (conflict-free frag loads)

typedef unsigned int u32;

// ---------------- scratch (static device globals; no allocation) ----------------
__device__ int   g_degcnt[N_NODES];
__device__ int   g_cursor[N_NODES];
__device__ int   g_rs[N_NODES + 1];
__device__ int   g_csr[N_EDGES];
__device__ int   g_bsum[GRID];
__device__ int   g_boff[GRID];
__device__ int   g_tile[4];              // gemm0, agg0, gemm1, agg1
__device__ float g_h[N_NODES * D];       // S0 then hidden h
__device__ float g_p[N_NODES * D];       // P (neighbor projection), reused per layer
__device__ u32   g_Wh[2][D * 128];       // [layer][k][n] tf32-hi of [Wself|Wneigh]
__device__ u32   g_Wl[2][D * 128];       // tf32-lo residual

// barrier state: monotonic, never reset (safe across graph replays)
__device__ unsigned g_bcnt = 0;
__device__ unsigned g_bgen = 0;

__device__ __forceinline__ void grid_bar() {
    __syncthreads();
    if (threadIdx.x == 0) {
        __threadfence();
        unsigned my = atomicAdd(&g_bcnt, 1u) + 1u;
        unsigned need = (my + GRID - 1u) / GRID;
        if ((my % GRID) == 0u) atomicAdd(&g_bgen, 1u);
        while (*((volatile unsigned*)&g_bgen) < need) {}
        __threadfence();
    }
    __syncthreads();
}

__device__ __forceinline__ int load_idx(const void* p, int e, bool is64) {
    return is64 ? (int)((const long long*)p)[e] : ((const int*)p)[e];
}

__device__ __forceinline__ u32 cvt_tf32(float x) {
    u32 r; asm("cvt.rna.tf32.f32 %0, %1;" : "=r"(r) : "f"(x)); return r;
}

__device__ __forceinline__ void mma_tf32(float* c, const u32* a, u32 b0, u32 b1) {
    asm volatile(
        "mma.sync.aligned.m16n8k8.row.col.f32.tf32.tf32.f32 "
        "{%0,%1,%2,%3}, {%4,%5,%6,%7}, {%8,%9}, {%0,%1,%2,%3};"
        : "+f"(c[0]), "+f"(c[1]), "+f"(c[2]), "+f"(c[3])
        : "r"(a[0]), "r"(a[1]), "r"(a[2]), "r"(a[3]), "r"(b0), "r"(b1));
}

// ---------------- shared memory ----------------
__shared__ __align__(16) u32 Ath[TILE * AT_ST];   // 17.4 KB tf32-hi tile
__shared__ __align__(16) u32 Atl[TILE * AT_ST];   // 17.4 KB tf32-lo tile
__shared__ int sscan[TPB];
__shared__ int rb[TILE + 1];
__shared__ int s_t;

// ---------------- dense projection: outS = inp@Ws, outP = inp@Wn (tensor cores) ----------------
__device__ void dense_proj(const float* __restrict__ inp,
                           float* __restrict__ outS, float* __restrict__ outP,
                           int l, int ctr, int tid) {
    const int lane = tid & 31;
    const int wid = tid >> 5;
    const int mgrp = wid & 3;            // 16-row group within 64-row tile
    const int cghalf = wid >> 1 & 0;     // placeholder (computed below)
    const int gid = lane >> 2;           // 0..7
    const int tig = lane & 3;            // 0..3
    const int whalf = wid >> 2;          // 0: S cols, 1: P cols
    (void)cghalf;

    const u32* Wh = g_Wh[l];
    const u32* Wl = g_Wl[l];

    for (;;) {
        __syncthreads();                 // protect Ath/Atl from previous tile's readers
        if (tid == 0) s_t = atomicAdd(&g_tile[ctr], 1);
        __syncthreads();
        const int t = s_t;
        if (t >= NT) break;
        const int row0 = t * TILE;

        // stage + convert A tile (64x64) to tf32 hi/lo
#pragma unroll
        for (int j = 0; j < 4; j++) {
            int idx = tid + j * TPB;     // 0..1023
            int r = idx >> 4, c = idx & 15;
            int gr = row0 + r;
            float4 v = make_float4(0.f, 0.f, 0.f, 0.f);
            if (gr < N_NODES) v = ((const float4*)(inp + (long long)gr * D))[c];
            u32* ph = &Ath[r * AT_ST + c * 4];
            u32* pl = &Atl[r * AT_ST + c * 4];
            u32 h0 = cvt_tf32(v.x), h1 = cvt_tf32(v.y);
            u32 h2 = cvt_tf32(v.z), h3 = cvt_tf32(v.w);
            ph[0] = h0; ph[1] = h1; ph[2] = h2; ph[3] = h3;
            pl[0] = __float_as_uint(v.x - __uint_as_float(h0));
            pl[1] = __float_as_uint(v.y - __uint_as_float(h1));
            pl[2] = __float_as_uint(v.z - __uint_as_float(h2));
            pl[3] = __float_as_uint(v.w - __uint_as_float(h3));
        }
        __syncthreads();

        // each warp: rows mgrp*16..+15 ; cols cg*32..+31 for cg in {whalf*2, whalf*2+1}
#pragma unroll
        for (int cgi = 0; cgi < 2; cgi++) {
            const int cg = whalf * 2 + cgi;      // 0,1 -> S ; 2,3 -> P
            float acc[4][4];
#pragma unroll
            for (int i = 0; i < 4; i++)
#pragma unroll
                for (int j = 0; j < 4; j++) acc[i][j] = 0.f;

#pragma unroll
            for (int ks = 0; ks < 8; ks++) {
                const int ar = mgrp * 16 + gid;
                const int ac = ks * 8 + tig;
                u32 ah[4], al[4];
                ah[0] = Ath[ar * AT_ST + ac];       al[0] = Atl[ar * AT_ST + ac];
                ah[1] = Ath[(ar + 8) * AT_ST + ac]; al[1] = Atl[(ar + 8) * AT_ST + ac];
                ah[2] = Ath[ar * AT_ST + ac + 4];   al[2] = Atl[ar * AT_ST + ac + 4];
                ah[3] = Ath[(ar + 8) * AT_ST + ac + 4]; al[3] = Atl[(ar + 8) * AT_ST + ac + 4];
#pragma unroll
                for (int nt = 0; nt < 4; nt++) {
                    const int n = cg * 32 + nt * 8 + gid;
                    const int k = ks * 8 + tig;
                    u32 bh0 = Wh[k * 128 + n];
                    u32 bh1 = Wh[(k + 4) * 128 + n];
                    u32 bl0 = Wl[k * 128 + n];
                    u32 bl1 = Wl[(k + 4) * 128 + n];
                    mma_tf32(acc[nt], ah, bh0, bh1);
                    mma_tf32(acc[nt], al, bh0, bh1);
                    mma_tf32(acc[nt], ah, bl0, bl1);
                }
            }
            // epilogue: store fragments
            float* dst = (cg < 2) ? outS : outP;
            const int cbase = (cg & 1) * 32;
#pragma unroll
            for (int nt = 0; nt < 4; nt++) {
                const int col = cbase + nt * 8 + 2 * tig;
                int r0 = row0 + mgrp * 16 + gid;
                if (r0 < N_NODES)
                    *(float2*)(dst + (long long)r0 * D + col) = make_float2(acc[nt][0], acc[nt][1]);
                int r1 = r0 + 8;
                if (r1 < N_NODES)
                    *(float2*)(dst + (long long)r1 * D + col) = make_float2(acc[nt][2], acc[nt][3]);
            }
        }
    }
}

// ---------------- aggregation: io[r] = [relu](io[r] + mean(g_p[neigh]) + b) ----------------
template <bool RELU>
__device__ void agg_combine(float* __restrict__ io, const float* __restrict__ bias,
                            int ctr, int tid) {
    const int hw = tid >> 4;             // halfwarp 0..15, owns rows hw*4..hw*4+3
    const int l16 = tid & 15;
    float4 bv = ((const float4*)bias)[l16];

    for (;;) {
        __syncthreads();
        if (tid == 0) s_t = atomicAdd(&g_tile[ctr], 1);
        __syncthreads();
        const int t = s_t;
        if (t >= NT) break;
        const int row0 = t * TILE;
        if (tid < TILE + 1) {
            int rr = row0 + tid; if (rr > N_NODES) rr = N_NODES;
            rb[tid] = g_rs[rr];
        }
        __syncthreads();
#pragma unroll
        for (int i = 0; i < 4; i++) {
            int r = hw * 4 + i;
            int gr = row0 + r;
            if (gr >= N_NODES) continue;
            float4 a0 = make_float4(0.f, 0.f, 0.f, 0.f), a1 = a0, a2 = a0, a3 = a0;
            int e = rb[r], lend = rb[r + 1];
            float iv = 1.0f / fmaxf((float)(lend - e), 1.0f);
            for (; e + 3 < lend; e += 4) {
                int s0 = g_csr[e],     s1 = g_csr[e + 1];
                int s2 = g_csr[e + 2], s3 = g_csr[e + 3];
                float4 v0 = __ldg((const float4*)(g_p + (long long)s0 * D) + l16);
                float4 v1 = __ldg((const float4*)(g_p + (long long)s1 * D) + l16);
                float4 v2 = __ldg((const float4*)(g_p + (long long)s2 * D) + l16);
                float4 v3 = __ldg((const float4*)(g_p + (long long)s3 * D) + l16);
                a0.x += v0.x; a0.y += v0.y; a0.z += v0.z; a0.w += v0.w;
                a1.x += v1.x; a1.y += v1.y; a1.z += v1.z; a1.w += v1.w;
                a2.x += v2.x; a2.y += v2.y; a2.z += v2.z; a2.w += v2.w;
                a3.x += v3.x; a3.y += v3.y; a3.z += v3.z; a3.w += v3.w;
            }
            for (; e < lend; e++) {
                int s0 = g_csr[e];
                float4 v0 = __ldg((const float4*)(g_p + (long long)s0 * D) + l16);
                a0.x += v0.x; a0.y += v0.y; a0.z += v0.z; a0.w += v0.w;
            }
            float4 s = *((float4*)(io + (long long)gr * D) + l16);
            float4 o;
            o.x = s.x + ((a0.x + a1.x) + (a2.x + a3.x)) * iv + bv.x;
            o.y = s.y + ((a0.y + a1.y) + (a2.y + a3.y)) * iv + bv.y;
            o.z = s.z + ((a0.z + a1.z) + (a2.z + a3.z)) * iv + bv.z;
            o.w = s.w + ((a0.w + a1.w) + (a2.w + a3.w)) * iv + bv.w;
            if (RELU) {
                o.x = fmaxf(o.x, 0.f); o.y = fmaxf(o.y, 0.f);
                o.z = fmaxf(o.z, 0.f); o.w = fmaxf(o.w, 0.f);
            }
            *((float4*)(io + (long long)gr * D) + l16) = o;
        }
    }
}

// ---------------- fused persistent kernel ----------------
__global__ void __launch_bounds__(TPB, 4)
sage_fused_kernel(const float* __restrict__ x,
                  const void* __restrict__ srcp,
                  const void* __restrict__ dstp,
                  const float* __restrict__ W_self0, const float* __restrict__ W_neigh0,
                  const float* __restrict__ b0,
                  const float* __restrict__ W_self1, const float* __restrict__ W_neigh1,
                  const float* __restrict__ b1,
                  float* __restrict__ outp) {
    const int tid = threadIdx.x;
    const int bid = blockIdx.x;
    const int gtid = bid * TPB + tid;
    const int gstride = GRID * TPB;

    // ---- index dtype detection ----
    if (tid == 0) sscan[0] = 0;
    __syncthreads();
    {
        int any = 0;
        const int* si = (const int*)srcp;
        for (int i = tid; i < 2048; i += TPB) any |= si[2 * i + 1];
        if (any) atomicOr(&sscan[0], 1);
    }
    __syncthreads();
    const bool is64 = (sscan[0] == 0);

    // ---- phase A: zero counters + convert weights to tf32 hi/lo planes ----
    for (int j = gtid; j < N_NODES; j += gstride) { g_degcnt[j] = 0; g_cursor[j] = 0; }
    if (gtid < 4) g_tile[gtid] = 0;
    {
        const float* Ws[2] = {W_self0, W_self1};
        const float* Wn[2] = {W_neigh0, W_neigh1};
        for (int idx = gtid; idx < 2 * D * 128; idx += gstride) {
            int l = idx >> 13;
            int rem = idx & 8191;
            int k = rem >> 7, n = rem & 127;
            float w = (n < D) ? Ws[l][k * D + n] : Wn[l][k * D + n - D];
            u32 h = cvt_tf32(w);
            g_Wh[l][rem] = h;
            g_Wl[l][rem] = __float_as_uint(w - __uint_as_float(h));
        }
    }
    grid_bar();

    // ---- phase B: degree histogram ----
    for (int e = gtid; e < N_EDGES; e += gstride)
        atomicAdd(&g_degcnt[load_idx(dstp, e, is64)], 1);
    grid_bar();

    // ---- phase C: per-block chunk sums ----
    {
        int n0 = bid * CH;
        int n = N_NODES - n0; if (n > CH) n = CH; if (n < 0) n = 0;
        int v = (tid < n) ? g_degcnt[n0 + tid] : 0;
        sscan[tid] = v; __syncthreads();
        for (int off = TPB / 2; off > 0; off >>= 1) {
            if (tid < off) sscan[tid] += sscan[tid + off];
            __syncthreads();
        }
        if (tid == 0) g_bsum[bid] = sscan[0];
    }
    grid_bar();

    // ---- phase D: block 0 scans the 592 chunk sums ----
    if (bid == 0) {
        int v[3]; int mysum = 0;
#pragma unroll
        for (int k = 0; k < 3; k++) {
            int idx = tid * 3 + k;
            v[k] = (idx < GRID) ? g_bsum[idx] : 0;
            mysum += v[k];
        }
        sscan[tid] = mysum; __syncthreads();
        for (int off = 1; off < TPB; off <<= 1) {
            int t2 = (tid >= off) ? sscan[tid - off] : 0;
            __syncthreads();
            sscan[tid] += t2;
            __syncthreads();
        }
        int run = sscan[tid] - mysum;
#pragma unroll
        for (int k = 0; k < 3; k++) {
            int idx = tid * 3 + k;
            if (idx < GRID) g_boff[idx] = run;
            run += v[k];
        }
    }
    grid_bar();

    // ---- phase E: per-chunk exclusive scan -> row starts ----
    {
        int n0 = bid * CH;
        int n = N_NODES - n0; if (n > CH) n = CH; if (n < 0) n = 0;
        int v = (tid < n) ? g_degcnt[n0 + tid] : 0;
        sscan[tid] = v; __syncthreads();
        for (int off = 1; off < TPB; off <<= 1) {
            int t2 = (tid >= off) ? sscan[tid - off] : 0;
            __syncthreads();
            sscan[tid] += t2;
            __syncthreads();
        }
        if (tid < n) g_rs[n0 + tid] = g_boff[bid] + sscan[tid] - v;
        if (bid == 0 && tid == 0) g_rs[N_NODES] = N_EDGES;
    }
    grid_bar();

    // ---- phase F: fill CSR ----
    for (int e = gtid; e < N_EDGES; e += gstride) {
        int dn = load_idx(dstp, e, is64);
        int s  = load_idx(srcp, e, is64);
        int pos = atomicAdd(&g_cursor[dn], 1);
        g_csr[g_rs[dn] + pos] = s;
    }
    grid_bar();

    // ---- phase G: GEMM-0: g_h = x@Ws0 (S0), g_p = x@Wn0 (P0) ----
    dense_proj(x, g_h, g_p, 0, 0, tid);
    grid_bar();

    // ---- phase H: agg0: g_h = relu(g_h + mean(g_p) + b0) ----
    agg_combine<true>(g_h, b0, 1, tid);
    grid_bar();

    // ---- phase I: GEMM-1: outp = g_h@Ws1 (S1), g_p = g_h@Wn1 (P1) ----
    dense_proj(g_h, outp, g_p, 1, 2, tid);
    grid_bar();

    // ---- phase J: agg1: outp = outp + mean(g_p) + b1 ----
    agg_combine<false>(outp, b1, 3, tid);
}

// ---------------- launch: ONE kernel = ONE graph node ----------------
extern "C" void kernel_launch(void* const* d_in, const int* in_sizes, int n_in,
                              void* d_out, int out_size) {
    const float* x        = (const float*)d_in[0];
    const void*  src      = d_in[1];
    const void*  dst      = d_in[2];
    const float* W_self0  = (const float*)d_in[3];
    const float* W_neigh0 = (const float*)d_in[4];
    const float* b0       = (const float*)d_in[5];
    const float* W_self1  = (const float*)d_in[6];
    const float* W_neigh1 = (const float*)d_in[7];
    const float* b1       = (const float*)d_in[8];
    float* outp = (float*)d_out;

    sage_fused_kernel<<<GRID, TPB>>>(x, src, dst,
                                     W_self0, W_neigh0, b0,
                                     W_self1, W_neigh1, b1, outp);
}

// round 11
// speedup vs baseline: 1.4337x; 1.4337x over previous
#include <cuda_runtime.h>
#include <cuda_fp16.h>

#define N_NODES 50000
#define N_EDGES 800000
#define D 64
#define GRID 592                         // 148 SMs x 4 blocks/SM
#define TPB 256
#define TILE 64
#define NT ((N_NODES + TILE - 1) / TILE) // 782 proj tiles of 64 rows
#define NWT (N_NODES / 8)                // 6250 agg warp-tiles of 8 rows (exact)
#define CH ((N_NODES + GRID - 1) / GRID) // 85 nodes per block chunk

typedef unsigned long long ull;
typedef unsigned int u32;

// ---------------- scratch (static device globals; no allocation) ----------------
__device__ int   g_degcnt[N_NODES];
__device__ int   g_cursor[N_NODES];
__device__ int   g_rs[N_NODES + 1];
__device__ int   g_csr[N_EDGES];
__device__ int   g_bsum[GRID];
__device__ int   g_boff[GRID];
__device__ int   g_tile[4];              // proj0, agg0, proj1, agg1
__device__ float g_h[N_NODES * D];       // S (self projection) then hidden h
__device__ u32   g_ph[N_NODES * (D / 2)];// P (neighbor projection) as half2

// barrier state: monotonic, never reset (safe across graph replays)
__device__ unsigned g_bcnt = 0;
__device__ unsigned g_bgen = 0;

__device__ __forceinline__ void grid_bar() {
    __syncthreads();
    if (threadIdx.x == 0) {
        __threadfence();
        unsigned my = atomicAdd(&g_bcnt, 1u) + 1u;
        unsigned need = (my + GRID - 1u) / GRID;
        if ((my % GRID) == 0u) atomicAdd(&g_bgen, 1u);
        while (*((volatile unsigned*)&g_bgen) < need) {}
        __threadfence();
    }
    __syncthreads();
}

__device__ __forceinline__ int load_idx(const void* p, int e, bool is64) {
    return is64 ? (int)((const long long*)p)[e] : ((const int*)p)[e];
}

// ---------------- f32x2 packed helpers ----------------
__device__ __forceinline__ ull pack2(float a) {
    ull r;
    asm("mov.b64 %0, {%1, %1};" : "=l"(r) : "r"(__float_as_uint(a)));
    return r;
}
__device__ __forceinline__ void ffma2(ull& d, ull a, ull b) {
    asm("fma.rn.f32x2 %0, %1, %2, %0;" : "+l"(d) : "l"(a), "l"(b));
}
__device__ __forceinline__ float lo2(ull v) { return __uint_as_float((unsigned)(v)); }
__device__ __forceinline__ float hi2(ull v) { return __uint_as_float((unsigned)(v >> 32)); }

// ---------------- shared memory ----------------
__shared__ __align__(16) float Wsm[2][D * D];   // 32 KB [Wself; Wneigh] of current layer
__shared__ __align__(16) float At[TILE][66];    // 16.9 KB staged input tile
__shared__ int sscan[TPB];
__shared__ int s_t;

// ---------------- dense projection: S = inp@Ws (fp32), P = inp@Wn (fp16) ----------------
__device__ void dense_proj(const float* __restrict__ inp, float* __restrict__ outS,
                           int ctr, int tid) {
    const int lane = tid & 31;
    const int w8 = (tid >> 5) * 8;       // warp owns rows w8..w8+7

    for (;;) {
        __syncthreads();                 // protect At from previous tile's readers
        if (tid == 0) s_t = atomicAdd(&g_tile[ctr], 1);
        __syncthreads();
        const int t = s_t;
        if (t >= NT) break;
        const int row0 = t * TILE;

        // stage A tile (64x64 fp32)
#pragma unroll
        for (int j = 0; j < 4; j++) {
            int idx = tid + j * TPB;
            int r = idx >> 4, c = idx & 15;
            int gr = row0 + r;
            float4 v = make_float4(0.f, 0.f, 0.f, 0.f);
            if (gr < N_NODES) v = ((const float4*)(inp + (long long)gr * D))[c];
            At[r][c * 4] = v.x; At[r][c * 4 + 1] = v.y;
            At[r][c * 4 + 2] = v.z; At[r][c * 4 + 3] = v.w;
        }
        __syncthreads();

        ull acc[8];
        // ---- pass 0: S = A@Ws ----
#pragma unroll
        for (int i = 0; i < 8; i++) acc[i] = 0;
#pragma unroll 2
        for (int k = 0; k < D; k += 2) {
            ull w0 = *(const ull*)&Wsm[0][k * D + 2 * lane];
            ull w1 = *(const ull*)&Wsm[0][(k + 1) * D + 2 * lane];
#pragma unroll
            for (int i = 0; i < 8; i++) {
                float2 a = *(const float2*)&At[w8 + i][k];
                ffma2(acc[i], pack2(a.x), w0);
                ffma2(acc[i], pack2(a.y), w1);
            }
        }
#pragma unroll
        for (int i = 0; i < 8; i++) {
            int gr = row0 + w8 + i;
            if (gr < N_NODES)
                *(float2*)(outS + (long long)gr * D + 2 * lane) = make_float2(lo2(acc[i]), hi2(acc[i]));
        }
        // ---- pass 1: P = A@Wn -> fp16 (At unchanged; no sync needed) ----
#pragma unroll
        for (int i = 0; i < 8; i++) acc[i] = 0;
#pragma unroll 2
        for (int k = 0; k < D; k += 2) {
            ull w0 = *(const ull*)&Wsm[1][k * D + 2 * lane];
            ull w1 = *(const ull*)&Wsm[1][(k + 1) * D + 2 * lane];
#pragma unroll
            for (int i = 0; i < 8; i++) {
                float2 a = *(const float2*)&At[w8 + i][k];
                ffma2(acc[i], pack2(a.x), w0);
                ffma2(acc[i], pack2(a.y), w1);
            }
        }
#pragma unroll
        for (int i = 0; i < 8; i++) {
            int gr = row0 + w8 + i;
            if (gr < N_NODES) {
                __half2 h = __float22half2_rn(make_float2(lo2(acc[i]), hi2(acc[i])));
                g_ph[gr * (D / 2) + lane] = *(u32*)&h;
            }
        }
    }
}

// ---------------- aggregation: io[r] = [relu](io[r] + mean(P[neigh]) + b) ----------------
// Per-warp 8-row tiles; quarter-warp (8 lanes) owns 2 rows; one fp16 row = 1 LDG.128.
template <bool RELU>
__device__ void agg_combine(float* __restrict__ io, const float* __restrict__ bias,
                            int ctr, int tid) {
    const int lane = tid & 31;
    const int q = lane >> 3;             // quarter-warp id 0..3
    const int lq = lane & 7;             // lane in quarter: halves 8*lq..8*lq+7
    float4 bv0 = *(const float4*)(bias + 8 * lq);
    float4 bv1 = *(const float4*)(bias + 8 * lq + 4);

    for (;;) {
        int t = 0;
        if (lane == 0) t = atomicAdd(&g_tile[ctr], 1);
        t = __shfl_sync(0xffffffffu, t, 0);
        if (t >= NWT) break;
        const int row0 = t * 8;

        int rsv = 0;
        if (lane < 9) rsv = g_rs[row0 + lane];

#pragma unroll
        for (int i = 0; i < 2; i++) {
            const int r = q * 2 + i;            // row within tile, 0..7
            const int gr = row0 + r;
            const int beg = __shfl_sync(0xffffffffu, rsv, r);
            const int end = __shfl_sync(0xffffffffu, rsv, r + 1);
            const float iv = 1.0f / fmaxf((float)(end - beg), 1.0f);

            float2 ac0 = make_float2(0.f, 0.f), ac1 = ac0, ac2 = ac0, ac3 = ac0;
            int e = beg;
            for (; e + 3 < end; e += 4) {
                int s0 = g_csr[e],     s1 = g_csr[e + 1];
                int s2 = g_csr[e + 2], s3 = g_csr[e + 3];
                uint4 u0 = __ldg((const uint4*)(g_ph + s0 * (D / 2)) + lq);
                uint4 u1 = __ldg((const uint4*)(g_ph + s1 * (D / 2)) + lq);
                uint4 u2 = __ldg((const uint4*)(g_ph + s2 * (D / 2)) + lq);
                uint4 u3 = __ldg((const uint4*)(g_ph + s3 * (D / 2)) + lq);
#define ACC8(U)                                                            \
                {                                                          \
                    float2 f;                                              \
                    f = __half22float2(*(__half2*)&(U).x); ac0.x += f.x; ac0.y += f.y; \
                    f = __half22float2(*(__half2*)&(U).y); ac1.x += f.x; ac1.y += f.y; \
                    f = __half22float2(*(__half2*)&(U).z); ac2.x += f.x; ac2.y += f.y; \
                    f = __half22float2(*(__half2*)&(U).w); ac3.x += f.x; ac3.y += f.y; \
                }
                ACC8(u0) ACC8(u1) ACC8(u2) ACC8(u3)
            }
            for (; e < end; e++) {
                int s0 = g_csr[e];
                uint4 u0 = __ldg((const uint4*)(g_ph + s0 * (D / 2)) + lq);
                ACC8(u0)
#undef ACC8
            }
            // combine with self projection + bias
            float4 s0v = *((const float4*)(io + (long long)gr * D + 8 * lq));
            float4 s1v = *((const float4*)(io + (long long)gr * D + 8 * lq + 4));
            float4 o0, o1;
            o0.x = s0v.x + ac0.x * iv + bv0.x;
            o0.y = s0v.y + ac0.y * iv + bv0.y;
            o0.z = s0v.z + ac1.x * iv + bv0.z;
            o0.w = s0v.w + ac1.y * iv + bv0.w;
            o1.x = s1v.x + ac2.x * iv + bv1.x;
            o1.y = s1v.y + ac2.y * iv + bv1.y;
            o1.z = s1v.z + ac3.x * iv + bv1.z;
            o1.w = s1v.w + ac3.y * iv + bv1.w;
            if (RELU) {
                o0.x = fmaxf(o0.x, 0.f); o0.y = fmaxf(o0.y, 0.f);
                o0.z = fmaxf(o0.z, 0.f); o0.w = fmaxf(o0.w, 0.f);
                o1.x = fmaxf(o1.x, 0.f); o1.y = fmaxf(o1.y, 0.f);
                o1.z = fmaxf(o1.z, 0.f); o1.w = fmaxf(o1.w, 0.f);
            }
            *((float4*)(io + (long long)gr * D + 8 * lq)) = o0;
            *((float4*)(io + (long long)gr * D + 8 * lq + 4)) = o1;
        }
    }
}

// ---------------- fused persistent kernel ----------------
__global__ void __launch_bounds__(TPB, 4)
sage_fused_kernel(const float* __restrict__ x,
                  const void* __restrict__ srcp,
                  const void* __restrict__ dstp,
                  const float* __restrict__ W_self0, const float* __restrict__ W_neigh0,
                  const float* __restrict__ b0,
                  const float* __restrict__ W_self1, const float* __restrict__ W_neigh1,
                  const float* __restrict__ b1,
                  float* __restrict__ outp) {
    const int tid = threadIdx.x;
    const int bid = blockIdx.x;
    const int gtid = bid * TPB + tid;
    const int gstride = GRID * TPB;

    // ---- index dtype detection ----
    if (tid == 0) sscan[0] = 0;
    __syncthreads();
    {
        int any = 0;
        const int* si = (const int*)srcp;
        for (int i = tid; i < 2048; i += TPB) any |= si[2 * i + 1];
        if (any) atomicOr(&sscan[0], 1);
    }
    __syncthreads();
    const bool is64 = (sscan[0] == 0);

    // ---- phase A: zero counters ----
    for (int j = gtid; j < N_NODES; j += gstride) { g_degcnt[j] = 0; g_cursor[j] = 0; }
    if (gtid < 4) g_tile[gtid] = 0;
    grid_bar();

    // ---- phase B: degree histogram ----
    for (int e = gtid; e < N_EDGES; e += gstride)
        atomicAdd(&g_degcnt[load_idx(dstp, e, is64)], 1);
    grid_bar();

    // ---- phase C: per-block chunk sums ----
    {
        int n0 = bid * CH;
        int n = N_NODES - n0; if (n > CH) n = CH; if (n < 0) n = 0;
        int v = (tid < n) ? g_degcnt[n0 + tid] : 0;
        sscan[tid] = v; __syncthreads();
        for (int off = TPB / 2; off > 0; off >>= 1) {
            if (tid < off) sscan[tid] += sscan[tid + off];
            __syncthreads();
        }
        if (tid == 0) g_bsum[bid] = sscan[0];
    }
    grid_bar();

    // ---- phase D: block 0 scans the 592 chunk sums ----
    if (bid == 0) {
        int v[3]; int mysum = 0;
#pragma unroll
        for (int k = 0; k < 3; k++) {
            int idx = tid * 3 + k;
            v[k] = (idx < GRID) ? g_bsum[idx] : 0;
            mysum += v[k];
        }
        sscan[tid] = mysum; __syncthreads();
        for (int off = 1; off < TPB; off <<= 1) {
            int t2 = (tid >= off) ? sscan[tid - off] : 0;
            __syncthreads();
            sscan[tid] += t2;
            __syncthreads();
        }
        int run = sscan[tid] - mysum;
#pragma unroll
        for (int k = 0; k < 3; k++) {
            int idx = tid * 3 + k;
            if (idx < GRID) g_boff[idx] = run;
            run += v[k];
        }
    }
    grid_bar();

    // ---- phase E: per-chunk exclusive scan -> row starts ----
    {
        int n0 = bid * CH;
        int n = N_NODES - n0; if (n > CH) n = CH; if (n < 0) n = 0;
        int v = (tid < n) ? g_degcnt[n0 + tid] : 0;
        sscan[tid] = v; __syncthreads();
        for (int off = 1; off < TPB; off <<= 1) {
            int t2 = (tid >= off) ? sscan[tid - off] : 0;
            __syncthreads();
            sscan[tid] += t2;
            __syncthreads();
        }
        if (tid < n) g_rs[n0 + tid] = g_boff[bid] + sscan[tid] - v;
        if (bid == 0 && tid == 0) g_rs[N_NODES] = N_EDGES;
    }
    grid_bar();

    // ---- phase F: fill CSR ----
    for (int e = gtid; e < N_EDGES; e += gstride) {
        int dn = load_idx(dstp, e, is64);
        int s  = load_idx(srcp, e, is64);
        int pos = atomicAdd(&g_cursor[dn], 1);
        g_csr[g_rs[dn] + pos] = s;
    }
    grid_bar();

    // ---- phase G: proj0: g_h = x@Ws0, g_ph = half(x@Wn0) ----
#pragma unroll
    for (int j = 0; j < 4; j++) {
        ((float4*)Wsm[0])[tid + j * TPB] = ((const float4*)W_self0)[tid + j * TPB];
        ((float4*)Wsm[1])[tid + j * TPB] = ((const float4*)W_neigh0)[tid + j * TPB];
    }
    __syncthreads();
    dense_proj(x, g_h, 0, tid);
    grid_bar();

    // ---- phase H: agg0: g_h = relu(g_h + mean(P0) + b0) ----
    agg_combine<true>(g_h, b0, 1, tid);
    grid_bar();

    // ---- phase I: proj1: outp = g_h@Ws1, g_ph = half(g_h@Wn1) ----
#pragma unroll
    for (int j = 0; j < 4; j++) {
        ((float4*)Wsm[0])[tid + j * TPB] = ((const float4*)W_self1)[tid + j * TPB];
        ((float4*)Wsm[1])[tid + j * TPB] = ((const float4*)W_neigh1)[tid + j * TPB];
    }
    __syncthreads();
    dense_proj(g_h, outp, 2, tid);
    grid_bar();

    // ---- phase J: agg1: outp = outp + mean(P1) + b1 ----
    agg_combine<false>(outp, b1, 3, tid);
}

// ---------------- launch: ONE kernel = ONE graph node ----------------
extern "C" void kernel_launch(void* const* d_in, const int* in_sizes, int n_in,
                              void* d_out, int out_size) {
    const float* x        = (const float*)d_in[0];
    const void*  src      = d_in[1];
    const void*  dst      = d_in[2];
    const float* W_self0  = (const float*)d_in[3];
    const float* W_neigh0 = (const float*)d_in[4];
    const float* b0       = (const float*)d_in[5];
    const float* W_self1  = (const float*)d_in[6];
    const float* W_neigh1 = (const float*)d_in[7];
    const float* b1       = (const float*)d_in[8];
    float* outp = (float*)d_out;

    sage_fused_kernel<<<GRID, TPB>>>(x, src, dst,
                                     W_self0, W_neigh0, b0,
                                     W_self1, W_neigh1, b1, outp);
}

// round 12
// speedup vs baseline: 1.5400x; 1.0741x over previous
#include <cuda_runtime.h>
#include <cuda_fp16.h>

#define N_NODES 50000
#define N_EDGES 800000
#define D 64
#define GRID 592                         // 148 SMs x 4 blocks/SM (co-resident, also on 152-SM GB300)
#define TPB 256
#define NCSR 200                         // blocks 0..199: CSR build; 200..591: proj0 overlap
#define CH 250                           // nodes per CSR-block chunk (200*250 = 50000 exact)
#define TILE 64
#define NT ((N_NODES + TILE - 1) / TILE) // 782 proj tiles
#define NWT4 (N_NODES / 4)               // 12500 agg warp-tiles of 4 rows

typedef unsigned long long ull;
typedef unsigned int u32;

// ---------------- scratch (static device globals; no allocation) ----------------
__device__ int   g_degcnt[N_NODES];
__device__ int   g_cursor[N_NODES];
__device__ int   g_rs[N_NODES + 1];
__device__ int   g_csr[N_EDGES];
__device__ int   g_bsum[NCSR];
__device__ int   g_boff[NCSR];
__device__ int   g_tile[4];              // proj0, agg0, proj1, agg1
__device__ float g_h[N_NODES * D];       // S (self projection) then hidden h
__device__ u32   g_ph[N_NODES * (D / 2)];// P (neighbor projection) as half2

// barrier state: monotonic, never reset (safe across graph replays)
// id 0: global (GRID blocks); id 1: CSR partial (NCSR blocks)
__device__ unsigned g_bc[2];
__device__ unsigned g_bg[2];

__device__ __forceinline__ void bar_n(int id, unsigned nblk) {
    __syncthreads();
    if (threadIdx.x == 0) {
        __threadfence();
        unsigned my = atomicAdd(&g_bc[id], 1u) + 1u;
        unsigned need = (my + nblk - 1u) / nblk;
        if ((my % nblk) == 0u) atomicAdd(&g_bg[id], 1u);
        while (*(volatile unsigned*)&g_bg[id] < need) {}
        __threadfence();
    }
    __syncthreads();
}

__device__ __forceinline__ int load_idx(const void* p, int e, bool is64) {
    return is64 ? (int)((const long long*)p)[e] : ((const int*)p)[e];
}

// ---------------- f32x2 packed helpers ----------------
__device__ __forceinline__ ull pack2(float a) {
    ull r;
    asm("mov.b64 %0, {%1, %1};" : "=l"(r) : "r"(__float_as_uint(a)));
    return r;
}
__device__ __forceinline__ void ffma2(ull& d, ull a, ull b) {
    asm("fma.rn.f32x2 %0, %1, %2, %0;" : "+l"(d) : "l"(a), "l"(b));
}
__device__ __forceinline__ float lo2(ull v) { return __uint_as_float((unsigned)(v)); }
__device__ __forceinline__ float hi2(ull v) { return __uint_as_float((unsigned)(v >> 32)); }

// ---------------- shared memory ----------------
__shared__ __align__(16) float Wsm[2][D * D];   // 32 KB
__shared__ __align__(16) float At[TILE][66];    // 16.9 KB
__shared__ int sscan[TPB];

// ---------------- dense projection: S = inp@Ws (fp32), P = inp@Wn (fp16) ----------------
__device__ void dense_proj(const float* __restrict__ inp, float* __restrict__ outS,
                           int ctr, int tid) {
    const int lane = tid & 31;
    const int w8 = (tid >> 5) * 8;
    __shared__ int s_t;

    for (;;) {
        __syncthreads();
        if (tid == 0) s_t = atomicAdd(&g_tile[ctr], 1);
        __syncthreads();
        const int t = s_t;
        if (t >= NT) break;
        const int row0 = t * TILE;

#pragma unroll
        for (int j = 0; j < 4; j++) {
            int idx = tid + j * TPB;
            int r = idx >> 4, c = idx & 15;
            int gr = row0 + r;
            float4 v = make_float4(0.f, 0.f, 0.f, 0.f);
            if (gr < N_NODES) v = ((const float4*)(inp + (long long)gr * D))[c];
            At[r][c * 4] = v.x; At[r][c * 4 + 1] = v.y;
            At[r][c * 4 + 2] = v.z; At[r][c * 4 + 3] = v.w;
        }
        __syncthreads();

        ull acc[8];
#pragma unroll
        for (int i = 0; i < 8; i++) acc[i] = 0;
#pragma unroll 2
        for (int k = 0; k < D; k += 2) {
            ull w0 = *(const ull*)&Wsm[0][k * D + 2 * lane];
            ull w1 = *(const ull*)&Wsm[0][(k + 1) * D + 2 * lane];
#pragma unroll
            for (int i = 0; i < 8; i++) {
                float2 a = *(const float2*)&At[w8 + i][k];
                ffma2(acc[i], pack2(a.x), w0);
                ffma2(acc[i], pack2(a.y), w1);
            }
        }
#pragma unroll
        for (int i = 0; i < 8; i++) {
            int gr = row0 + w8 + i;
            if (gr < N_NODES)
                *(float2*)(outS + (long long)gr * D + 2 * lane) = make_float2(lo2(acc[i]), hi2(acc[i]));
        }
#pragma unroll
        for (int i = 0; i < 8; i++) acc[i] = 0;
#pragma unroll 2
        for (int k = 0; k < D; k += 2) {
            ull w0 = *(const ull*)&Wsm[1][k * D + 2 * lane];
            ull w1 = *(const ull*)&Wsm[1][(k + 1) * D + 2 * lane];
#pragma unroll
            for (int i = 0; i < 8; i++) {
                float2 a = *(const float2*)&At[w8 + i][k];
                ffma2(acc[i], pack2(a.x), w0);
                ffma2(acc[i], pack2(a.y), w1);
            }
        }
#pragma unroll
        for (int i = 0; i < 8; i++) {
            int gr = row0 + w8 + i;
            if (gr < N_NODES) {
                __half2 h = __float22half2_rn(make_float2(lo2(acc[i]), hi2(acc[i])));
                g_ph[gr * (D / 2) + lane] = *(u32*)&h;
            }
        }
    }
}

// ---------------- aggregation: io[r] = [relu](io[r] + mean(P[neigh]) + b) ----------------
// warp-tile = 4 rows; quarter-warp (8 lanes) owns ONE row; fp16 row = 1 LDG.128 per quarter.
template <bool RELU>
__device__ void agg_combine(float* __restrict__ io, const float* __restrict__ bias,
                            int ctr, int tid) {
    const int lane = tid & 31;
    const int q = lane >> 3;
    const int lq = lane & 7;
    float4 bv0 = *(const float4*)(bias + 8 * lq);
    float4 bv1 = *(const float4*)(bias + 8 * lq + 4);

    for (;;) {
        int t = 0;
        if (lane == 0) t = atomicAdd(&g_tile[ctr], 1);
        t = __shfl_sync(0xffffffffu, t, 0);
        if (t >= NWT4) break;
        const int row0 = t * 4;

        int rsv = 0;
        if (lane < 5) rsv = g_rs[row0 + lane];
        const int beg = __shfl_sync(0xffffffffu, rsv, q);
        const int end = __shfl_sync(0xffffffffu, rsv, q + 1);
        const int gr = row0 + q;
        const float iv = 1.0f / fmaxf((float)(end - beg), 1.0f);

        float2 ac0 = make_float2(0.f, 0.f), ac1 = ac0, ac2 = ac0, ac3 = ac0;
        int e = beg;
        for (; e + 3 < end; e += 4) {
            int s0 = g_csr[e],     s1 = g_csr[e + 1];
            int s2 = g_csr[e + 2], s3 = g_csr[e + 3];
            uint4 u0 = __ldg((const uint4*)(g_ph + s0 * (D / 2)) + lq);
            uint4 u1 = __ldg((const uint4*)(g_ph + s1 * (D / 2)) + lq);
            uint4 u2 = __ldg((const uint4*)(g_ph + s2 * (D / 2)) + lq);
            uint4 u3 = __ldg((const uint4*)(g_ph + s3 * (D / 2)) + lq);
#define ACC8(U)                                                                        \
            {                                                                          \
                float2 f;                                                              \
                f = __half22float2(*(__half2*)&(U).x); ac0.x += f.x; ac0.y += f.y;     \
                f = __half22float2(*(__half2*)&(U).y); ac1.x += f.x; ac1.y += f.y;     \
                f = __half22float2(*(__half2*)&(U).z); ac2.x += f.x; ac2.y += f.y;     \
                f = __half22float2(*(__half2*)&(U).w); ac3.x += f.x; ac3.y += f.y;     \
            }
            ACC8(u0) ACC8(u1) ACC8(u2) ACC8(u3)
        }
        for (; e < end; e++) {
            int s0 = g_csr[e];
            uint4 u0 = __ldg((const uint4*)(g_ph + s0 * (D / 2)) + lq);
            ACC8(u0)
#undef ACC8
        }
        float4 s0v = *((const float4*)(io + (long long)gr * D + 8 * lq));
        float4 s1v = *((const float4*)(io + (long long)gr * D + 8 * lq + 4));
        float4 o0, o1;
        o0.x = s0v.x + ac0.x * iv + bv0.x;
        o0.y = s0v.y + ac0.y * iv + bv0.y;
        o0.z = s0v.z + ac1.x * iv + bv0.z;
        o0.w = s0v.w + ac1.y * iv + bv0.w;
        o1.x = s1v.x + ac2.x * iv + bv1.x;
        o1.y = s1v.y + ac2.y * iv + bv1.y;
        o1.z = s1v.z + ac3.x * iv + bv1.z;
        o1.w = s1v.w + ac3.y * iv + bv1.w;
        if (RELU) {
            o0.x = fmaxf(o0.x, 0.f); o0.y = fmaxf(o0.y, 0.f);
            o0.z = fmaxf(o0.z, 0.f); o0.w = fmaxf(o0.w, 0.f);
            o1.x = fmaxf(o1.x, 0.f); o1.y = fmaxf(o1.y, 0.f);
            o1.z = fmaxf(o1.z, 0.f); o1.w = fmaxf(o1.w, 0.f);
        }
        *((float4*)(io + (long long)gr * D + 8 * lq)) = o0;
        *((float4*)(io + (long long)gr * D + 8 * lq + 4)) = o1;
    }
}

// ---------------- fused persistent kernel ----------------
__global__ void __launch_bounds__(TPB, 4)
sage_fused_kernel(const float* __restrict__ x,
                  const void* __restrict__ srcp,
                  const void* __restrict__ dstp,
                  const float* __restrict__ W_self0, const float* __restrict__ W_neigh0,
                  const float* __restrict__ b0,
                  const float* __restrict__ W_self1, const float* __restrict__ W_neigh1,
                  const float* __restrict__ b1,
                  float* __restrict__ outp) {
    const int tid = threadIdx.x;
    const int bid = blockIdx.x;

    // ---- index dtype detection (cheap; every block identical) ----
    if (tid == 0) sscan[0] = 0;
    __syncthreads();
    {
        int any = 0;
        const int* si = (const int*)srcp;
        for (int i = tid; i < 2048; i += TPB) any |= si[2 * i + 1];
        if (any) atomicOr(&sscan[0], 1);
    }
    __syncthreads();
    const bool is64 = (sscan[0] == 0);

    if (bid < NCSR) {
        // ================= CSR-builder role =================
        const int gt = bid * TPB + tid;
        const int gs = NCSR * TPB;
        // zero counters (g_tile[0] was reset at end of previous replay)
        for (int j = gt; j < N_NODES; j += gs) { g_degcnt[j] = 0; g_cursor[j] = 0; }
        if (gt >= 1 && gt < 4) g_tile[gt] = 0;   // agg0/proj1/agg1 counters
        bar_n(1, NCSR);
        // histogram
        for (int e = gt; e < N_EDGES; e += gs)
            atomicAdd(&g_degcnt[load_idx(dstp, e, is64)], 1);
        bar_n(1, NCSR);
        // per-block chunk sums (CH=250 > TPB? no: 250 <= 256)
        {
            int n0 = bid * CH;
            int v = (tid < CH) ? g_degcnt[n0 + tid] : 0;
            sscan[tid] = v; __syncthreads();
            for (int off = TPB / 2; off > 0; off >>= 1) {
                if (tid < off) sscan[tid] += sscan[tid + off];
                __syncthreads();
            }
            if (tid == 0) g_bsum[bid] = sscan[0];
        }
        bar_n(1, NCSR);
        // block 0 scans the 200 chunk sums
        if (bid == 0) {
            int v = (tid < NCSR) ? g_bsum[tid] : 0;
            sscan[tid] = v; __syncthreads();
            for (int off = 1; off < TPB; off <<= 1) {
                int t2 = (tid >= off) ? sscan[tid - off] : 0;
                __syncthreads();
                sscan[tid] += t2;
                __syncthreads();
            }
            if (tid < NCSR) g_boff[tid] = sscan[tid] - v;
        }
        bar_n(1, NCSR);
        // per-chunk exclusive scan -> row starts
        {
            int n0 = bid * CH;
            int v = (tid < CH) ? g_degcnt[n0 + tid] : 0;
            sscan[tid] = v; __syncthreads();
            for (int off = 1; off < TPB; off <<= 1) {
                int t2 = (tid >= off) ? sscan[tid - off] : 0;
                __syncthreads();
                sscan[tid] += t2;
                __syncthreads();
            }
            if (tid < CH) g_rs[n0 + tid] = g_boff[bid] + sscan[tid] - v;
            if (bid == 0 && tid == 0) g_rs[N_NODES] = N_EDGES;
        }
        bar_n(1, NCSR);
        // fill CSR
        for (int e = gt; e < N_EDGES; e += gs) {
            int dn = load_idx(dstp, e, is64);
            int s  = load_idx(srcp, e, is64);
            int pos = atomicAdd(&g_cursor[dn], 1);
            g_csr[g_rs[dn] + pos] = s;
        }
    } else {
        // ================= proj0 role (overlapped with CSR build) =================
#pragma unroll
        for (int j = 0; j < 4; j++) {
            ((float4*)Wsm[0])[tid + j * TPB] = ((const float4*)W_self0)[tid + j * TPB];
            ((float4*)Wsm[1])[tid + j * TPB] = ((const float4*)W_neigh0)[tid + j * TPB];
        }
        __syncthreads();
        dense_proj(x, g_h, 0, tid);
    }
    bar_n(0, GRID);

    // ---- agg0: g_h = relu(g_h + mean(P0) + b0) ----
    agg_combine<true>(g_h, b0, 1, tid);
    bar_n(0, GRID);

    // ---- proj1: outp = g_h@Ws1, g_ph = half(g_h@Wn1) ----
#pragma unroll
    for (int j = 0; j < 4; j++) {
        ((float4*)Wsm[0])[tid + j * TPB] = ((const float4*)W_self1)[tid + j * TPB];
        ((float4*)Wsm[1])[tid + j * TPB] = ((const float4*)W_neigh1)[tid + j * TPB];
    }
    __syncthreads();
    dense_proj(g_h, outp, 2, tid);
    bar_n(0, GRID);

    // ---- agg1: outp = outp + mean(P1) + b1 ----
    agg_combine<false>(outp, b1, 3, tid);

    // ---- final barrier, then reset the pre-barrier counter for the next replay ----
    bar_n(0, GRID);
    if (bid == 0 && tid == 0) g_tile[0] = 0;
}

// ---------------- launch: ONE kernel = ONE graph node ----------------
extern "C" void kernel_launch(void* const* d_in, const int* in_sizes, int n_in,
                              void* d_out, int out_size) {
    const float* x        = (const float*)d_in[0];
    const void*  src      = d_in[1];
    const void*  dst      = d_in[2];
    const float* W_self0  = (const float*)d_in[3];
    const float* W_neigh0 = (const float*)d_in[4];
    const float* b0       = (const float*)d_in[5];
    const float* W_self1  = (const float*)d_in[6];
    const float* W_neigh1 = (const float*)d_in[7];
    const float* b1       = (const float*)d_in[8];
    float* outp = (float*)d_out;

    sage_fused_kernel<<<GRID, TPB>>>(x, src, dst,
                                     W_self0, W_neigh0, b0,
                                     W_self1, W_neigh1, b1, outp);
}

// round 13
// speedup vs baseline: 2.2034x; 1.4308x over previous
#include <cuda_runtime.h>
#include <cuda_fp16.h>

#define N_NODES 50000
#define N_EDGES 800000
#define D 64
#define GRID 592                         // 148 SMs x 4 blocks/SM
#define TPB 256
#define NCSR 200                         // blocks 0..199: CSR build; rest: proj0 overlap
#define CH 250                           // 200*250 = 50000 exact
#define TILE 32
#define NT ((N_NODES + TILE - 1) / TILE) // 1563 proj tiles
#define NWT4 (N_NODES / 4)               // 12500 agg warp-tiles of 4 rows
#define A_ST 72                          // A smem stride (halves): 144B -> 4-bank row step
#define W_ST 136                         // W smem stride (halves): 272B -> 4-bank row step

typedef unsigned long long ull;
typedef unsigned int u32;

// ---------------- scratch (static device globals; no allocation) ----------------
__device__ int   g_degcnt[N_NODES];
__device__ int   g_cursor[N_NODES];
__device__ int   g_rs[N_NODES + 1];
__device__ int   g_csr[N_EDGES];
__device__ int   g_bsum[NCSR];
__device__ int   g_boff[NCSR];
__device__ int   g_tile[4];              // proj0, agg0, proj1, agg1
__device__ float g_h[N_NODES * D];       // S then hidden h
__device__ u32   g_ph[N_NODES * (D / 2)];// P as half2

// barrier state: monotonic (replay-safe). id 0: global; id 1: CSR partial
__device__ unsigned g_bc[2];
__device__ unsigned g_bg[2];

__device__ __forceinline__ void bar_n(int id, unsigned nblk) {
    __syncthreads();
    if (threadIdx.x == 0) {
        __threadfence();
        unsigned my = atomicAdd(&g_bc[id], 1u) + 1u;
        unsigned need = (my + nblk - 1u) / nblk;
        if ((my % nblk) == 0u) atomicAdd(&g_bg[id], 1u);
        while (*(volatile unsigned*)&g_bg[id] < need) {}
        __threadfence();
    }
    __syncthreads();
}

__device__ __forceinline__ int load_idx(const void* p, int e, bool is64) {
    return is64 ? (int)((const long long*)p)[e] : ((const int*)p)[e];
}

// ---------------- mma helpers ----------------
__device__ __forceinline__ void ldsm_x4(u32& r0, u32& r1, u32& r2, u32& r3, u32 addr) {
    asm volatile("ldmatrix.sync.aligned.m8n8.x4.shared.b16 {%0,%1,%2,%3}, [%4];"
                 : "=r"(r0), "=r"(r1), "=r"(r2), "=r"(r3) : "r"(addr));
}
__device__ __forceinline__ void ldsm_x2_t(u32& r0, u32& r1, u32 addr) {
    asm volatile("ldmatrix.sync.aligned.m8n8.x2.trans.shared.b16 {%0,%1}, [%2];"
                 : "=r"(r0), "=r"(r1) : "r"(addr));
}
__device__ __forceinline__ void mma16816(float* c, const u32* a, u32 b0, u32 b1) {
    asm volatile(
        "mma.sync.aligned.m16n8k16.row.col.f32.f16.f16.f32 "
        "{%0,%1,%2,%3}, {%4,%5,%6,%7}, {%8,%9}, {%0,%1,%2,%3};"
        : "+f"(c[0]), "+f"(c[1]), "+f"(c[2]), "+f"(c[3])
        : "r"(a[0]), "r"(a[1]), "r"(a[2]), "r"(a[3]), "r"(b0), "r"(b1));
}

// ---------------- shared memory ----------------
__shared__ __align__(16) __half Ah[TILE * A_ST];   // 4.6 KB
__shared__ __align__(16) __half Wh[D * W_ST];      // 17.4 KB  [k][n: Ws|Wn] fp16
__shared__ int sscan[TPB];

// ---------------- W staging (once per proj phase) ----------------
__device__ __forceinline__ void stage_W(const float* __restrict__ Ws,
                                        const float* __restrict__ Wn, int tid) {
    for (int idx = tid; idx < D * 128; idx += TPB) {
        int k = idx >> 7, n = idx & 127;
        float w = (n < D) ? Ws[k * D + n] : Wn[k * D + (n - D)];
        Wh[k * W_ST + n] = __float2half(w);
    }
}

// ---------------- dense projection via HMMA: S = inp@Ws (fp32), P = inp@Wn (fp16) ----------------
__device__ void dense_proj(const float* __restrict__ inp, float* __restrict__ outS,
                           int ctr, int tid) {
    const int lane = tid & 31;
    const int w = tid >> 5;
    const int mg = w & 1;                // 16-row group
    const int nq = w >> 1;               // 32-col group: 0,1 -> S ; 2,3 -> P
    const int gid = lane >> 2;
    const int tig = lane & 3;
    __shared__ int s_t;

    // per-lane ldmatrix smem addresses (byte offsets within shared window)
    const u32 ah_base = (u32)__cvta_generic_to_shared(Ah);
    const u32 wh_base = (u32)__cvta_generic_to_shared(Wh);
    const u32 a_lane = ah_base + ((mg * 16 + (lane & 15)) * A_ST + (lane >> 4) * 8) * 2;
    const u32 b_lane = wh_base + ((lane & 15) * W_ST + nq * 32) * 2;

    for (;;) {
        __syncthreads();
        if (tid == 0) s_t = atomicAdd(&g_tile[ctr], 1);
        __syncthreads();
        const int t = s_t;
        if (t >= NT) break;
        const int row0 = t * TILE;

        // stage A tile (32 x 64 fp16); thread -> row tid>>3, cols (tid&7)*8..+7
        {
            int r = tid >> 3, c = (tid & 7) * 8;
            int gr = row0 + r;
            float4 v0 = make_float4(0.f, 0.f, 0.f, 0.f), v1 = v0;
            if (gr < N_NODES) {
                v0 = *(const float4*)(inp + (long long)gr * D + c);
                v1 = *(const float4*)(inp + (long long)gr * D + c + 4);
            }
            __half2 h0 = __float22half2_rn(make_float2(v0.x, v0.y));
            __half2 h1 = __float22half2_rn(make_float2(v0.z, v0.w));
            __half2 h2 = __float22half2_rn(make_float2(v1.x, v1.y));
            __half2 h3 = __float22half2_rn(make_float2(v1.z, v1.w));
            uint4 pk;
            pk.x = *(u32*)&h0; pk.y = *(u32*)&h1; pk.z = *(u32*)&h2; pk.w = *(u32*)&h3;
            *(uint4*)&Ah[r * A_ST + c] = pk;
        }
        __syncthreads();

        float acc[4][4];
#pragma unroll
        for (int i = 0; i < 4; i++)
#pragma unroll
            for (int j = 0; j < 4; j++) acc[i][j] = 0.f;

#pragma unroll
        for (int kb = 0; kb < 4; kb++) {
            u32 a0, a1, a2, a3;
            ldsm_x4(a0, a1, a2, a3, a_lane + kb * 32);   // 16 halves = 32B per kb
            u32 af[4] = {a0, a1, a2, a3};
#pragma unroll
            for (int nb = 0; nb < 4; nb++) {
                u32 b0, b1;
                ldsm_x2_t(b0, b1, b_lane + (kb * 16 * W_ST + nb * 8) * 2);
                mma16816(acc[nb], af, b0, b1);
            }
        }

        // epilogue
        const int r0g = row0 + mg * 16 + gid;
        const int r1g = r0g + 8;
        if (nq < 2) {
#pragma unroll
            for (int nb = 0; nb < 4; nb++) {
                int col = nq * 32 + nb * 8 + tig * 2;
                if (r0g < N_NODES)
                    *(float2*)(outS + (long long)r0g * D + col) = make_float2(acc[nb][0], acc[nb][1]);
                if (r1g < N_NODES)
                    *(float2*)(outS + (long long)r1g * D + col) = make_float2(acc[nb][2], acc[nb][3]);
            }
        } else {
#pragma unroll
            for (int nb = 0; nb < 4; nb++) {
                int col = (nq - 2) * 32 + nb * 8 + tig * 2;
                if (r0g < N_NODES) {
                    __half2 h = __float22half2_rn(make_float2(acc[nb][0], acc[nb][1]));
                    g_ph[r0g * (D / 2) + (col >> 1)] = *(u32*)&h;
                }
                if (r1g < N_NODES) {
                    __half2 h = __float22half2_rn(make_float2(acc[nb][2], acc[nb][3]));
                    g_ph[r1g * (D / 2) + (col >> 1)] = *(u32*)&h;
                }
            }
        }
    }
}

// ---------------- aggregation: io[r] = [relu](io[r] + mean(P[neigh]) + b) ----------------
template <bool RELU>
__device__ void agg_combine(float* __restrict__ io, const float* __restrict__ bias,
                            int ctr, int tid) {
    const int lane = tid & 31;
    const int q = lane >> 3;
    const int lq = lane & 7;
    float4 bv0 = *(const float4*)(bias + 8 * lq);
    float4 bv1 = *(const float4*)(bias + 8 * lq + 4);

    for (;;) {
        int t = 0;
        if (lane == 0) t = atomicAdd(&g_tile[ctr], 1);
        t = __shfl_sync(0xffffffffu, t, 0);
        if (t >= NWT4) break;
        const int row0 = t * 4;

        int rsv = 0;
        if (lane < 5) rsv = g_rs[row0 + lane];
        const int beg = __shfl_sync(0xffffffffu, rsv, q);
        const int end = __shfl_sync(0xffffffffu, rsv, q + 1);
        const int gr = row0 + q;
        const float iv = 1.0f / fmaxf((float)(end - beg), 1.0f);

        float2 ac0 = make_float2(0.f, 0.f), ac1 = ac0, ac2 = ac0, ac3 = ac0;
        int e = beg;
        for (; e + 3 < end; e += 4) {
            int s0 = g_csr[e],     s1 = g_csr[e + 1];
            int s2 = g_csr[e + 2], s3 = g_csr[e + 3];
            uint4 u0 = __ldg((const uint4*)(g_ph + s0 * (D / 2)) + lq);
            uint4 u1 = __ldg((const uint4*)(g_ph + s1 * (D / 2)) + lq);
            uint4 u2 = __ldg((const uint4*)(g_ph + s2 * (D / 2)) + lq);
            uint4 u3 = __ldg((const uint4*)(g_ph + s3 * (D / 2)) + lq);
#define ACC8(U)                                                                        \
            {                                                                          \
                float2 f;                                                              \
                f = __half22float2(*(__half2*)&(U).x); ac0.x += f.x; ac0.y += f.y;     \
                f = __half22float2(*(__half2*)&(U).y); ac1.x += f.x; ac1.y += f.y;     \
                f = __half22float2(*(__half2*)&(U).z); ac2.x += f.x; ac2.y += f.y;     \
                f = __half22float2(*(__half2*)&(U).w); ac3.x += f.x; ac3.y += f.y;     \
            }
            ACC8(u0) ACC8(u1) ACC8(u2) ACC8(u3)
        }
        for (; e < end; e++) {
            int s0 = g_csr[e];
            uint4 u0 = __ldg((const uint4*)(g_ph + s0 * (D / 2)) + lq);
            ACC8(u0)
#undef ACC8
        }
        float4 s0v = *((const float4*)(io + (long long)gr * D + 8 * lq));
        float4 s1v = *((const float4*)(io + (long long)gr * D + 8 * lq + 4));
        float4 o0, o1;
        o0.x = s0v.x + ac0.x * iv + bv0.x;
        o0.y = s0v.y + ac0.y * iv + bv0.y;
        o0.z = s0v.z + ac1.x * iv + bv0.z;
        o0.w = s0v.w + ac1.y * iv + bv0.w;
        o1.x = s1v.x + ac2.x * iv + bv1.x;
        o1.y = s1v.y + ac2.y * iv + bv1.y;
        o1.z = s1v.z + ac3.x * iv + bv1.z;
        o1.w = s1v.w + ac3.y * iv + bv1.w;
        if (RELU) {
            o0.x = fmaxf(o0.x, 0.f); o0.y = fmaxf(o0.y, 0.f);
            o0.z = fmaxf(o0.z, 0.f); o0.w = fmaxf(o0.w, 0.f);
            o1.x = fmaxf(o1.x, 0.f); o1.y = fmaxf(o1.y, 0.f);
            o1.z = fmaxf(o1.z, 0.f); o1.w = fmaxf(o1.w, 0.f);
        }
        *((float4*)(io + (long long)gr * D + 8 * lq)) = o0;
        *((float4*)(io + (long long)gr * D + 8 * lq + 4)) = o1;
    }
}

// ---------------- fused persistent kernel ----------------
__global__ void __launch_bounds__(TPB, 4)
sage_fused_kernel(const float* __restrict__ x,
                  const void* __restrict__ srcp,
                  const void* __restrict__ dstp,
                  const float* __restrict__ W_self0, const float* __restrict__ W_neigh0,
                  const float* __restrict__ b0,
                  const float* __restrict__ W_self1, const float* __restrict__ W_neigh1,
                  const float* __restrict__ b1,
                  float* __restrict__ outp) {
    const int tid = threadIdx.x;
    const int bid = blockIdx.x;

    // ---- index dtype detection ----
    if (tid == 0) sscan[0] = 0;
    __syncthreads();
    {
        int any = 0;
        const int* si = (const int*)srcp;
        for (int i = tid; i < 2048; i += TPB) any |= si[2 * i + 1];
        if (any) atomicOr(&sscan[0], 1);
    }
    __syncthreads();
    const bool is64 = (sscan[0] == 0);

    if (bid < NCSR) {
        // ================= CSR-builder role =================
        const int gt = bid * TPB + tid;
        const int gs = NCSR * TPB;
        for (int j = gt; j < N_NODES; j += gs) { g_degcnt[j] = 0; g_cursor[j] = 0; }
        if (gt >= 1 && gt < 4) g_tile[gt] = 0;
        bar_n(1, NCSR);
        for (int e = gt; e < N_EDGES; e += gs)
            atomicAdd(&g_degcnt[load_idx(dstp, e, is64)], 1);
        bar_n(1, NCSR);
        {
            int n0 = bid * CH;
            int v = (tid < CH) ? g_degcnt[n0 + tid] : 0;
            sscan[tid] = v; __syncthreads();
            for (int off = TPB / 2; off > 0; off >>= 1) {
                if (tid < off) sscan[tid] += sscan[tid + off];
                __syncthreads();
            }
            if (tid == 0) g_bsum[bid] = sscan[0];
        }
        bar_n(1, NCSR);
        if (bid == 0) {
            int v = (tid < NCSR) ? g_bsum[tid] : 0;
            sscan[tid] = v; __syncthreads();
            for (int off = 1; off < TPB; off <<= 1) {
                int t2 = (tid >= off) ? sscan[tid - off] : 0;
                __syncthreads();
                sscan[tid] += t2;
                __syncthreads();
            }
            if (tid < NCSR) g_boff[tid] = sscan[tid] - v;
        }
        bar_n(1, NCSR);
        {
            int n0 = bid * CH;
            int v = (tid < CH) ? g_degcnt[n0 + tid] : 0;
            sscan[tid] = v; __syncthreads();
            for (int off = 1; off < TPB; off <<= 1) {
                int t2 = (tid >= off) ? sscan[tid - off] : 0;
                __syncthreads();
                sscan[tid] += t2;
                __syncthreads();
            }
            if (tid < CH) g_rs[n0 + tid] = g_boff[bid] + sscan[tid] - v;
            if (bid == 0 && tid == 0) g_rs[N_NODES] = N_EDGES;
        }
        bar_n(1, NCSR);
        for (int e = gt; e < N_EDGES; e += gs) {
            int dn = load_idx(dstp, e, is64);
            int s  = load_idx(srcp, e, is64);
            int pos = atomicAdd(&g_cursor[dn], 1);
            g_csr[g_rs[dn] + pos] = s;
        }
    } else {
        // ================= proj0 role (overlapped) =================
        stage_W(W_self0, W_neigh0, tid);
        __syncthreads();
        dense_proj(x, g_h, 0, tid);
    }
    bar_n(0, GRID);

    // ---- agg0: g_h = relu(g_h + mean(P0) + b0) ----
    agg_combine<true>(g_h, b0, 1, tid);
    bar_n(0, GRID);

    // ---- proj1: outp = g_h@Ws1, g_ph = half(g_h@Wn1) ----
    stage_W(W_self1, W_neigh1, tid);
    __syncthreads();
    dense_proj(g_h, outp, 2, tid);
    bar_n(0, GRID);

    // ---- agg1: outp = outp + mean(P1) + b1 ----
    agg_combine<false>(outp, b1, 3, tid);

    bar_n(0, GRID);
    if (bid == 0 && tid == 0) g_tile[0] = 0;
}

// ---------------- launch: ONE kernel = ONE graph node ----------------
extern "C" void kernel_launch(void* const* d_in, const int* in_sizes, int n_in,
                              void* d_out, int out_size) {
    const float* x        = (const float*)d_in[0];
    const void*  src      = d_in[1];
    const void*  dst      = d_in[2];
    const float* W_self0  = (const float*)d_in[3];
    const float* W_neigh0 = (const float*)d_in[4];
    const float* b0       = (const float*)d_in[5];
    const float* W_self1  = (const float*)d_in[6];
    const float* W_neigh1 = (const float*)d_in[7];
    const float* b1       = (const float*)d_in[8];
    float* outp = (float*)d_out;

    sage_fused_kernel<<<GRID, TPB>>>(x, src, dst,
                                     W_self0, W_neigh0, b0,
                                     W_self1, W_neigh1, b1, outp);
}